// round 16
// baseline (speedup 1.0000x reference)
#include <cuda_runtime.h>
#include <cuda_fp16.h>
#include <cstdint>

#define BATCH 4
#define SEQ 2048
#define DMODEL 2048
#define NH 16
#define NKV 4
#define HD 128
#define MROWS (BATCH * SEQ)   // 8192
#define KVN 1024              // fused K|V projection width

// ---------------- scratch (device globals: allocation-free) ----------------
__device__ __half g_xh[(size_t)MROWS * DMODEL];
__device__ __half g_wqh[(size_t)DMODEL * NH * HD];
__device__ __half g_wkvh[(size_t)DMODEL * KVN];
__device__ __half g_woh[(size_t)NH * HD * DMODEL];
__device__ __half g_qh[(size_t)MROWS * NH * HD];
__device__ __half g_kh[(size_t)MROWS * NKV * HD];
__device__ __half g_vh[(size_t)MROWS * NKV * HD];
__device__ __half g_oh[(size_t)MROWS * NH * HD];

// ---------------- helpers ---------------------------------------------------
__device__ __forceinline__ uint32_t smem_u32(const void* p) {
    uint32_t a;
    asm("{ .reg .u64 t; cvta.to.shared.u64 t, %1; cvt.u32.u64 %0, t; }"
        : "=r"(a) : "l"(p));
    return a;
}

__device__ __forceinline__ void mma16(float c[4], const uint32_t a[4], const uint32_t b[2]) {
    asm volatile(
        "mma.sync.aligned.m16n8k16.row.col.f32.f16.f16.f32 "
        "{%0,%1,%2,%3}, {%4,%5,%6,%7}, {%8,%9}, {%0,%1,%2,%3};"
        : "+f"(c[0]), "+f"(c[1]), "+f"(c[2]), "+f"(c[3])
        : "r"(a[0]), "r"(a[1]), "r"(a[2]), "r"(a[3]), "r"(b[0]), "r"(b[1]));
}

#define LDSM4(r0, r1, r2, r3, addr)                                              \
    asm volatile("ldmatrix.sync.aligned.m8n8.x4.shared.b16 {%0,%1,%2,%3}, [%4];" \
        : "=r"(r0), "=r"(r1), "=r"(r2), "=r"(r3) : "r"(addr))
#define LDSM4T(r0, r1, r2, r3, addr)                                             \
    asm volatile("ldmatrix.sync.aligned.m8n8.x4.trans.shared.b16 {%0,%1,%2,%3}, [%4];" \
        : "=r"(r0), "=r"(r1), "=r"(r2), "=r"(r3) : "r"(addr))
#define CPA16(sa, gp) \
    asm volatile("cp.async.cg.shared.global [%0], [%1], 16;" :: "r"(sa), "l"(gp))
#define CPA_COMMIT() asm volatile("cp.async.commit_group;" ::: "memory")
#define CPA_WAIT(n)  asm volatile("cp.async.wait_group %0;" :: "n"(n) : "memory")

// ------- merged convert: x | wq | wk,wv packed -> wkv | wo, one launch ------
#define NX4   (MROWS * DMODEL / 4)            // 4194304
#define NWQ4  (DMODEL * NH * HD / 4)          // 1048576
#define NWKV4 (DMODEL * NKV * HD / 4)         // 262144
#define C1 NX4
#define C2 (C1 + NWQ4)
#define C3 (C2 + NWKV4)
#define C4 (C3 + NWKV4)
#define C5 (C4 + NWQ4)                        // wo same size as wq
__global__ void f2hpack(const float* __restrict__ x,  __half* __restrict__ xh,
                        const float* __restrict__ wq, __half* __restrict__ wqh,
                        const float* __restrict__ wk, const float* __restrict__ wv,
                        __half* __restrict__ wkvh,
                        const float* __restrict__ wo, __half* __restrict__ woh) {
    int i = blockIdx.x * blockDim.x + threadIdx.x;
    if (i >= C5) return;
    if (i < C1) {
        float4 v = ((const float4*)x)[i];
        ((__half2*)xh)[2 * i]     = __floats2half2_rn(v.x, v.y);
        ((__half2*)xh)[2 * i + 1] = __floats2half2_rn(v.z, v.w);
    } else if (i < C2) {
        int j = i - C1;
        float4 v = ((const float4*)wq)[j];
        ((__half2*)wqh)[2 * j]     = __floats2half2_rn(v.x, v.y);
        ((__half2*)wqh)[2 * j + 1] = __floats2half2_rn(v.z, v.w);
    } else if (i < C3) {                       // wk [2048,512] -> wkv cols 0..511
        int j = i - C2;
        int row = j >> 7, col4 = j & 127;
        float4 v = ((const float4*)wk)[j];
        __half* d = wkvh + (size_t)row * KVN + col4 * 4;
        ((__half2*)d)[0] = __floats2half2_rn(v.x, v.y);
        ((__half2*)d)[1] = __floats2half2_rn(v.z, v.w);
    } else if (i < C4) {                       // wv [2048,512] -> wkv cols 512..1023
        int j = i - C3;
        int row = j >> 7, col4 = j & 127;
        float4 v = ((const float4*)wv)[j];
        __half* d = wkvh + (size_t)row * KVN + 512 + col4 * 4;
        ((__half2*)d)[0] = __floats2half2_rn(v.x, v.y);
        ((__half2*)d)[1] = __floats2half2_rn(v.z, v.w);
    } else {
        int j = i - C4;
        float4 v = ((const float4*)wo)[j];
        ((__half2*)woh)[2 * j]     = __floats2half2_rn(v.x, v.y);
        ((__half2*)woh)[2 * j + 1] = __floats2half2_rn(v.z, v.w);
    }
}

// ---------------- half GEMM: C[M,N] = A[M,K] @ B[K,N] ----------------------
// MODE 1: half out + RoPE all cols (Q).  MODE 2: float out (wo).
// MODE 5: fused KV -> split outputs: col<512 rope->Cv(kh), else ->Cv2(vh).
// CTA tile 128x128, k-tile 64, 3-stage cp.async pipeline.
#define GEMM_SMEM_BYTES 107520
template <int MODE>
__global__ __launch_bounds__(256, 2)
void gemm_h(const __half* __restrict__ A, const __half* __restrict__ B,
            void* __restrict__ Cv, void* __restrict__ Cv2, int N, int K,
            const float* __restrict__ fc, const float* __restrict__ fs) {
    extern __shared__ char sm[];
    const uint32_t sb = smem_u32(sm);
    const int tid  = threadIdx.x;
    const int lane = tid & 31, w = tid >> 5;
    const int g = lane >> 2, c = lane & 3;
    const int wm = (w & 3) * 32, wn = (w >> 2) * 64;
    const int m0 = blockIdx.y * 128, n0 = blockIdx.x * 128;

    const int lmrow = (lane & 7) + ((lane >> 3) & 1) * 8;
    const int lmcol = (lane >> 4) * 4;
    const int vrow  = (lane & 7) + ((lane >> 3) & 1) * 8;
    const int vcolw = (lane >> 4) * 4;

    const int ar = tid >> 3, ach = tid & 7;
    const int br16 = tid >> 4, bch = tid & 15;

    const int nt = K >> 6;
    float acc[2][8][4] = {};

    auto issue = [&](int t, int s) {
        const int k0 = t << 6;
        const uint32_t st = sb + (uint32_t)s * 35840u;
        #pragma unroll
        for (int p = 0; p < 4; p++) {
            int r = ar + 32 * p;
            CPA16(st + (uint32_t)(r * 144 + ach * 16),
                  A + (size_t)(m0 + r) * K + k0 + ach * 8);
        }
        #pragma unroll
        for (int p = 0; p < 4; p++) {
            int r = br16 + 16 * p;
            CPA16(st + 18432u + (uint32_t)(r * 272 + bch * 16),
                  B + (size_t)(k0 + r) * N + n0 + bch * 8);
        }
        CPA_COMMIT();
    };

    issue(0, 0);
    if (nt > 1) issue(1, 1);

    for (int i = 0; i < nt; i++) {
        const int s = i % 3;
        if (i == nt - 1) { CPA_WAIT(0); } else { CPA_WAIT(1); }
        __syncthreads();

        const uint32_t sA = sb + (uint32_t)s * 35840u;
        const uint32_t sB = sA + 18432u;
        #pragma unroll
        for (int ks = 0; ks < 4; ks++) {
            uint32_t a[2][4];
            #pragma unroll
            for (int mf = 0; mf < 2; mf++)
                LDSM4(a[mf][0], a[mf][1], a[mf][2], a[mf][3],
                      sA + (uint32_t)(((wm + mf * 16 + lmrow) * 36 + ks * 8 + lmcol) * 4));
            const uint32_t baddr = sB +
                (uint32_t)(((ks * 16 + vrow) * 68 + (wn >> 1) + vcolw) * 4);
            #pragma unroll
            for (int nf2 = 0; nf2 < 4; nf2++) {
                uint32_t d0, d1, d2, d3;
                LDSM4T(d0, d1, d2, d3, baddr + (uint32_t)(nf2 * 32));
                uint32_t bA[2] = {d0, d1}, bB[2] = {d2, d3};
                #pragma unroll
                for (int mf = 0; mf < 2; mf++) {
                    mma16(acc[mf][2 * nf2],     a[mf], bA);
                    mma16(acc[mf][2 * nf2 + 1], a[mf], bB);
                }
            }
        }
        if (i + 2 < nt) issue(i + 2, (i + 2) % 3);
    }

    #pragma unroll
    for (int mf = 0; mf < 2; mf++) {
        const int r0 = m0 + wm + mf * 16 + g;
        const int s0 = r0 & (SEQ - 1), s1 = (r0 + 8) & (SEQ - 1);
        #pragma unroll
        for (int nf = 0; nf < 8; nf++) {
            const int col = n0 + wn + nf * 8 + 2 * c;
            float a0 = acc[mf][nf][0], a1 = acc[mf][nf][1];
            float a2 = acc[mf][nf][2], a3 = acc[mf][nf][3];
            const bool dorope = (MODE == 1) || (MODE == 5 && col < 512);
            if (dorope) {
                const int i2 = (col & (HD - 1)) >> 1;
                float c0 = fc[s0 * (HD / 2) + i2], sn0 = fs[s0 * (HD / 2) + i2];
                float c1 = fc[s1 * (HD / 2) + i2], sn1 = fs[s1 * (HD / 2) + i2];
                float t0 = a0 * c0 - a1 * sn0, t1 = a0 * sn0 + a1 * c0;
                float t2 = a2 * c1 - a3 * sn1, t3 = a2 * sn1 + a3 * c1;
                a0 = t0; a1 = t1; a2 = t2; a3 = t3;
            }
            if (MODE == 2) {
                float* C = (float*)Cv;
                *(float2*)(C + (size_t)r0 * N + col)       = make_float2(a0, a1);
                *(float2*)(C + (size_t)(r0 + 8) * N + col) = make_float2(a2, a3);
            } else if (MODE == 5) {
                __half* Kd = (__half*)Cv;
                __half* Vd = (__half*)Cv2;
                if (col < 512) {
                    *(__half2*)(Kd + (size_t)r0 * 512 + col)       = __floats2half2_rn(a0, a1);
                    *(__half2*)(Kd + (size_t)(r0 + 8) * 512 + col) = __floats2half2_rn(a2, a3);
                } else {
                    *(__half2*)(Vd + (size_t)r0 * 512 + col - 512)       = __floats2half2_rn(a0, a1);
                    *(__half2*)(Vd + (size_t)(r0 + 8) * 512 + col - 512) = __floats2half2_rn(a2, a3);
                }
            } else {
                __half* C = (__half*)Cv;
                *(__half2*)(C + (size_t)r0 * N + col)       = __floats2half2_rn(a0, a1);
                *(__half2*)(C + (size_t)(r0 + 8) * N + col) = __floats2half2_rn(a2, a3);
            }
        }
    }
}

// ---------------- flash attention, fp16 mma, causal, GQA -------------------
// CTA: 128 Q rows, 8 warps x 16 rows; K/V tile 64. Grid (SEQ/128, NH, B).
// Compact q/k/v buffers (R14 layout). Longest-first: qt = 15 - blockIdx.x.
#define ATT_SMEM_BYTES 88064
__global__ __launch_bounds__(256)
void attn_f16(const __half* __restrict__ q, const __half* __restrict__ k,
              const __half* __restrict__ v, __half* __restrict__ o) {
    extern __shared__ uint32_t smu[];
    uint32_t* sp = smu + 17408;
    const uint32_t sqb = smem_u32(smu);
    const uint32_t skb = sqb + 8704 * 4;
    const uint32_t svb = sqb + 13056 * 4;
    const uint32_t spb = sqb + 17408 * 4;

    const int tid  = threadIdx.x;
    const int lane = tid & 31, w = tid >> 5;
    const int g = lane >> 2, c = lane & 3;
    const int qt = (SEQ / 128 - 1) - blockIdx.x;   // longest first
    const int h = blockIdx.y, b = blockIdx.z;
    const int kv = h >> 2;
    const size_t rowbase = (size_t)b * SEQ;
    const int qrow0 = qt * 128;
    const int r0g = w * 16 + g;

    const int lmrow = (lane & 7) + ((lane >> 3) & 1) * 8;
    const int lmcol = (lane >> 4) * 4;
    const int krow  = (lane & 7) + (lane >> 4) * 8;
    const int kcolw = ((lane >> 3) & 1) * 4;
    const int vrow  = (lane & 7) + ((lane >> 3) & 1) * 8;
    const int vcolw = (lane >> 4) * 4;

    const int sr16 = tid >> 4, sch = tid & 15;

    #pragma unroll
    for (int p = 0; p < 8; p++) {
        int r = sr16 + 16 * p;
        CPA16(sqb + (uint32_t)(r * 272 + sch * 16),
              q + (rowbase + qrow0 + r) * (NH * HD) + h * HD + sch * 8);
    }
    CPA_COMMIT();

    float out[16][4] = {};
    float m0 = -1e30f, m1 = -1e30f, l0 = 0.f, l1 = 0.f;
    const float SCALE = 0.08838834764831845f;   // 1/sqrt(128)

    const int ktmax = 2 * qt + 1;
    for (int kt = 0; kt <= ktmax; kt++) {
        __syncthreads();
        #pragma unroll
        for (int p = 0; p < 4; p++) {
            int r = sr16 + 16 * p;
            size_t src = (rowbase + kt * 64 + r) * (NKV * HD) + kv * HD + sch * 8;
            CPA16(skb + (uint32_t)(r * 272 + sch * 16), k + src);
            CPA16(svb + (uint32_t)(r * 272 + sch * 16), v + src);
        }
        CPA_COMMIT();
        CPA_WAIT(0);
        __syncthreads();

        float s[8][4] = {};
        #pragma unroll
        for (int ks = 0; ks < 8; ks++) {
            uint32_t a[4];
            LDSM4(a[0], a[1], a[2], a[3],
                  sqb + (uint32_t)(((w * 16 + lmrow) * 68 + ks * 8 + lmcol) * 4));
            #pragma unroll
            for (int nfp = 0; nfp < 4; nfp++) {
                uint32_t b0, b1, b2, b3;
                LDSM4(b0, b1, b2, b3,
                      skb + (uint32_t)(((nfp * 16 + krow) * 68 + ks * 8 + kcolw) * 4));
                uint32_t bA[2] = {b0, b1}, bB[2] = {b2, b3};
                mma16(s[2 * nfp],     a, bA);
                mma16(s[2 * nfp + 1], a, bB);
            }
        }

        const bool needmask = (kt >= 2 * qt);
        const int grow0 = qrow0 + r0g, grow1 = grow0 + 8;
        #pragma unroll
        for (int nf = 0; nf < 8; nf++) {
            int col = kt * 64 + nf * 8 + 2 * c;
            s[nf][0] = (needmask && col     > grow0) ? -1e30f : s[nf][0] * SCALE;
            s[nf][1] = (needmask && col + 1 > grow0) ? -1e30f : s[nf][1] * SCALE;
            s[nf][2] = (needmask && col     > grow1) ? -1e30f : s[nf][2] * SCALE;
            s[nf][3] = (needmask && col + 1 > grow1) ? -1e30f : s[nf][3] * SCALE;
        }

        float rm0 = -1e30f, rm1 = -1e30f;
        #pragma unroll
        for (int nf = 0; nf < 8; nf++) {
            rm0 = fmaxf(rm0, fmaxf(s[nf][0], s[nf][1]));
            rm1 = fmaxf(rm1, fmaxf(s[nf][2], s[nf][3]));
        }
        #pragma unroll
        for (int off = 1; off < 4; off <<= 1) {
            rm0 = fmaxf(rm0, __shfl_xor_sync(0xffffffffu, rm0, off));
            rm1 = fmaxf(rm1, __shfl_xor_sync(0xffffffffu, rm1, off));
        }
        float mn0 = fmaxf(m0, rm0), mn1 = fmaxf(m1, rm1);
        float co0 = __expf(m0 - mn0), co1 = __expf(m1 - mn1);
        m0 = mn0; m1 = mn1;

        float rs0 = 0.f, rs1 = 0.f;
        #pragma unroll
        for (int nf = 0; nf < 8; nf++) {
            float p00 = __expf(s[nf][0] - mn0);
            float p01 = __expf(s[nf][1] - mn0);
            float p10 = __expf(s[nf][2] - mn1);
            float p11 = __expf(s[nf][3] - mn1);
            rs0 += p00 + p01;
            rs1 += p10 + p11;
            __half2 h0 = __floats2half2_rn(p00, p01);
            __half2 h1 = __floats2half2_rn(p10, p11);
            sp[r0g * 36 + nf * 4 + c]       = *(uint32_t*)&h0;
            sp[(r0g + 8) * 36 + nf * 4 + c] = *(uint32_t*)&h1;
        }
        #pragma unroll
        for (int off = 1; off < 4; off <<= 1) {
            rs0 += __shfl_xor_sync(0xffffffffu, rs0, off);
            rs1 += __shfl_xor_sync(0xffffffffu, rs1, off);
        }
        l0 = l0 * co0 + rs0;
        l1 = l1 * co1 + rs1;
        #pragma unroll
        for (int nf = 0; nf < 16; nf++) {
            out[nf][0] *= co0; out[nf][1] *= co0;
            out[nf][2] *= co1; out[nf][3] *= co1;
        }
        __syncwarp();

        #pragma unroll
        for (int ks = 0; ks < 4; ks++) {
            uint32_t a[4];
            LDSM4(a[0], a[1], a[2], a[3],
                  spb + (uint32_t)(((w * 16 + lmrow) * 36 + ks * 8 + lmcol) * 4));
            const uint32_t rowaddr = svb + (uint32_t)(((ks * 16 + vrow) * 68 + vcolw) * 4);
            #pragma unroll
            for (int nf2 = 0; nf2 < 8; nf2++) {
                uint32_t d0, d1, d2, d3;
                LDSM4T(d0, d1, d2, d3, rowaddr + (uint32_t)(nf2 * 32));
                uint32_t bA[2] = {d0, d1}, bB[2] = {d2, d3};
                mma16(out[2 * nf2],     a, bA);
                mma16(out[2 * nf2 + 1], a, bB);
            }
        }
        __syncwarp();
    }

    const float i0 = 1.f / l0, i1 = 1.f / l1;
    const size_t gr0 = rowbase + qrow0 + r0g;
    #pragma unroll
    for (int nf = 0; nf < 16; nf++) {
        const int col = h * HD + nf * 8 + 2 * c;
        *(__half2*)(o + gr0 * (NH * HD) + col) =
            __floats2half2_rn(out[nf][0] * i0, out[nf][1] * i0);
        *(__half2*)(o + (gr0 + 8) * (NH * HD) + col) =
            __floats2half2_rn(out[nf][2] * i1, out[nf][3] * i1);
    }
}

// ---------------- launch ----------------------------------------------------
extern "C" void kernel_launch(void* const* d_in, const int* in_sizes, int n_in,
                              void* d_out, int out_size) {
    const float* x  = (const float*)d_in[0];
    const float* fc = (const float*)d_in[1];
    const float* fs = (const float*)d_in[2];
    const float* wq = (const float*)d_in[3];
    const float* wk = (const float*)d_in[4];
    const float* wv = (const float*)d_in[5];
    const float* wo = (const float*)d_in[6];
    float* out = (float*)d_out;

    __half *xh, *wqh, *wkvh, *woh, *qh, *kh, *vh, *oh;
    cudaGetSymbolAddress((void**)&xh,   g_xh);
    cudaGetSymbolAddress((void**)&wqh,  g_wqh);
    cudaGetSymbolAddress((void**)&wkvh, g_wkvh);
    cudaGetSymbolAddress((void**)&woh,  g_woh);
    cudaGetSymbolAddress((void**)&qh,   g_qh);
    cudaGetSymbolAddress((void**)&kh,   g_kh);
    cudaGetSymbolAddress((void**)&vh,   g_vh);
    cudaGetSymbolAddress((void**)&oh,   g_oh);

    cudaFuncSetAttribute(attn_f16, cudaFuncAttributeMaxDynamicSharedMemorySize,
                         ATT_SMEM_BYTES);
    cudaFuncSetAttribute(gemm_h<1>, cudaFuncAttributeMaxDynamicSharedMemorySize,
                         GEMM_SMEM_BYTES);
    cudaFuncSetAttribute(gemm_h<2>, cudaFuncAttributeMaxDynamicSharedMemorySize,
                         GEMM_SMEM_BYTES);
    cudaFuncSetAttribute(gemm_h<5>, cudaFuncAttributeMaxDynamicSharedMemorySize,
                         GEMM_SMEM_BYTES);

    // convert + pack weights, one launch
    f2hpack<<<(C5 + 255) / 256, 256>>>(x, xh, wq, wqh, wk, wv, wkvh, wo, woh);

    // Q projection + RoPE
    gemm_h<1><<<dim3((NH * HD) / 128, MROWS / 128), 256, GEMM_SMEM_BYTES>>>(
        xh, wqh, qh, nullptr, NH * HD, DMODEL, fc, fs);

    // fused K+V projection; epilogue splits into compact kh (rope) / vh
    gemm_h<5><<<dim3(KVN / 128, MROWS / 128), 256, GEMM_SMEM_BYTES>>>(
        xh, wkvh, kh, vh, KVN, DMODEL, fc, fs);

    // attention (compact buffers, longest-first)
    attn_f16<<<dim3(SEQ / 128, NH, BATCH), 256, ATT_SMEM_BYTES>>>(qh, kh, vh, oh);

    // output projection (float out)
    gemm_h<2><<<dim3(DMODEL / 128, MROWS / 128), 256, GEMM_SMEM_BYTES>>>(
        oh, woh, out, nullptr, DMODEL, DMODEL, nullptr, nullptr);
}

// round 17
// speedup vs baseline: 1.6745x; 1.6745x over previous
#include <cuda_runtime.h>
#include <cuda_fp16.h>
#include <cstdint>

#define BATCH 4
#define SEQ 2048
#define DMODEL 2048
#define NH 16
#define NKV 4
#define HD 128
#define MROWS (BATCH * SEQ)   // 8192

// ---------------- scratch (device globals: allocation-free) ----------------
__device__ __half g_xh[(size_t)MROWS * DMODEL];
__device__ __half g_wqh[(size_t)DMODEL * NH * HD];
__device__ __half g_wkh[(size_t)DMODEL * NKV * HD];
__device__ __half g_wvh[(size_t)DMODEL * NKV * HD];
__device__ __half g_woh[(size_t)NH * HD * DMODEL];
__device__ __half g_qh[(size_t)MROWS * NH * HD];
__device__ __half g_kh[(size_t)MROWS * NKV * HD];
__device__ __half g_vh[(size_t)MROWS * NKV * HD];
__device__ __half g_oh[(size_t)MROWS * NH * HD];

// ---------------- helpers ---------------------------------------------------
__device__ __forceinline__ uint32_t smem_u32(const void* p) {
    uint32_t a;
    asm("{ .reg .u64 t; cvta.to.shared.u64 t, %1; cvt.u32.u64 %0, t; }"
        : "=r"(a) : "l"(p));
    return a;
}

__device__ __forceinline__ void mma16(float c[4], const uint32_t a[4], const uint32_t b[2]) {
    asm volatile(
        "mma.sync.aligned.m16n8k16.row.col.f32.f16.f16.f32 "
        "{%0,%1,%2,%3}, {%4,%5,%6,%7}, {%8,%9}, {%0,%1,%2,%3};"
        : "+f"(c[0]), "+f"(c[1]), "+f"(c[2]), "+f"(c[3])
        : "r"(a[0]), "r"(a[1]), "r"(a[2]), "r"(a[3]), "r"(b[0]), "r"(b[1]));
}

#define LDSM4(r0, r1, r2, r3, addr)                                              \
    asm volatile("ldmatrix.sync.aligned.m8n8.x4.shared.b16 {%0,%1,%2,%3}, [%4];" \
        : "=r"(r0), "=r"(r1), "=r"(r2), "=r"(r3) : "r"(addr))
#define LDSM4T(r0, r1, r2, r3, addr)                                             \
    asm volatile("ldmatrix.sync.aligned.m8n8.x4.trans.shared.b16 {%0,%1,%2,%3}, [%4];" \
        : "=r"(r0), "=r"(r1), "=r"(r2), "=r"(r3) : "r"(addr))
#define CPA16(sa, gp) \
    asm volatile("cp.async.cg.shared.global [%0], [%1], 16;" :: "r"(sa), "l"(gp))
#define CPA_COMMIT() asm volatile("cp.async.commit_group;" ::: "memory")
#define CPA_WAIT(n)  asm volatile("cp.async.wait_group %0;" :: "n"(n) : "memory")

// ---------------- merged fp32 -> fp16 convert (5 segments, 1 launch) --------
#define NX4   (MROWS * DMODEL / 4)            // 4194304
#define NWQ4  (DMODEL * NH * HD / 4)          // 1048576
#define NWKV4 (DMODEL * NKV * HD / 4)         // 262144
#define C1 NX4
#define C2 (C1 + NWQ4)
#define C3 (C2 + NWKV4)
#define C4 (C3 + NWKV4)
#define C5 (C4 + NWQ4)                        // wo same size as wq
__global__ void f2h5(const float* __restrict__ x,  __half* __restrict__ xh,
                     const float* __restrict__ wq, __half* __restrict__ wqh,
                     const float* __restrict__ wk, __half* __restrict__ wkh,
                     const float* __restrict__ wv, __half* __restrict__ wvh,
                     const float* __restrict__ wo, __half* __restrict__ woh) {
    int i = blockIdx.x * blockDim.x + threadIdx.x;
    if (i >= C5) return;
    const float* s; __half* d; int j;
    if      (i < C1) { s = x;  d = xh;  j = i; }
    else if (i < C2) { s = wq; d = wqh; j = i - C1; }
    else if (i < C3) { s = wk; d = wkh; j = i - C2; }
    else if (i < C4) { s = wv; d = wvh; j = i - C3; }
    else             { s = wo; d = woh; j = i - C4; }
    float4 v = ((const float4*)s)[j];
    ((__half2*)d)[2 * j]     = __floats2half2_rn(v.x, v.y);
    ((__half2*)d)[2 * j + 1] = __floats2half2_rn(v.z, v.w);
}

// ---------------- half GEMM: C[M,N] = A[M,K] @ B[K,N] ----------------------
// MODE 0: half out. MODE 1: half out + fused RoPE. MODE 2: float out.
// CTA tile 128x128, k-tile 64, 3-stage cp.async pipeline.
#define GEMM_SMEM_BYTES 107520
template <int MODE>
__global__ __launch_bounds__(256, 2)
void gemm_h(const __half* __restrict__ A, const __half* __restrict__ B,
            void* __restrict__ Cv, int N, int K,
            const float* __restrict__ fc, const float* __restrict__ fs) {
    extern __shared__ char sm[];
    const uint32_t sb = smem_u32(sm);
    const int tid  = threadIdx.x;
    const int lane = tid & 31, w = tid >> 5;
    const int g = lane >> 2, c = lane & 3;
    const int wm = (w & 3) * 32, wn = (w >> 2) * 64;
    const int m0 = blockIdx.y * 128, n0 = blockIdx.x * 128;

    const int lmrow = (lane & 7) + ((lane >> 3) & 1) * 8;
    const int lmcol = (lane >> 4) * 4;
    const int vrow  = (lane & 7) + ((lane >> 3) & 1) * 8;
    const int vcolw = (lane >> 4) * 4;

    const int ar = tid >> 3, ach = tid & 7;
    const int br16 = tid >> 4, bch = tid & 15;

    const int nt = K >> 6;
    float acc[2][8][4] = {};

    auto issue = [&](int t, int s) {
        const int k0 = t << 6;
        const uint32_t st = sb + (uint32_t)s * 35840u;
        #pragma unroll
        for (int p = 0; p < 4; p++) {
            int r = ar + 32 * p;
            CPA16(st + (uint32_t)(r * 144 + ach * 16),
                  A + (size_t)(m0 + r) * K + k0 + ach * 8);
        }
        #pragma unroll
        for (int p = 0; p < 4; p++) {
            int r = br16 + 16 * p;
            CPA16(st + 18432u + (uint32_t)(r * 272 + bch * 16),
                  B + (size_t)(k0 + r) * N + n0 + bch * 8);
        }
        CPA_COMMIT();
    };

    issue(0, 0);
    if (nt > 1) issue(1, 1);

    for (int i = 0; i < nt; i++) {
        const int s = i % 3;
        if (i == nt - 1) { CPA_WAIT(0); } else { CPA_WAIT(1); }
        __syncthreads();

        const uint32_t sA = sb + (uint32_t)s * 35840u;
        const uint32_t sB = sA + 18432u;
        #pragma unroll
        for (int ks = 0; ks < 4; ks++) {
            uint32_t a[2][4];
            #pragma unroll
            for (int mf = 0; mf < 2; mf++)
                LDSM4(a[mf][0], a[mf][1], a[mf][2], a[mf][3],
                      sA + (uint32_t)(((wm + mf * 16 + lmrow) * 36 + ks * 8 + lmcol) * 4));
            const uint32_t baddr = sB +
                (uint32_t)(((ks * 16 + vrow) * 68 + (wn >> 1) + vcolw) * 4);
            #pragma unroll
            for (int nf2 = 0; nf2 < 4; nf2++) {
                uint32_t d0, d1, d2, d3;
                LDSM4T(d0, d1, d2, d3, baddr + (uint32_t)(nf2 * 32));
                uint32_t bA[2] = {d0, d1}, bB[2] = {d2, d3};
                #pragma unroll
                for (int mf = 0; mf < 2; mf++) {
                    mma16(acc[mf][2 * nf2],     a[mf], bA);
                    mma16(acc[mf][2 * nf2 + 1], a[mf], bB);
                }
            }
        }
        if (i + 2 < nt) issue(i + 2, (i + 2) % 3);
    }

    #pragma unroll
    for (int mf = 0; mf < 2; mf++) {
        const int r0 = m0 + wm + mf * 16 + g;
        const int s0 = r0 & (SEQ - 1), s1 = (r0 + 8) & (SEQ - 1);
        #pragma unroll
        for (int nf = 0; nf < 8; nf++) {
            const int col = n0 + wn + nf * 8 + 2 * c;
            float a0 = acc[mf][nf][0], a1 = acc[mf][nf][1];
            float a2 = acc[mf][nf][2], a3 = acc[mf][nf][3];
            if (MODE == 1) {
                const int i2 = (col & (HD - 1)) >> 1;
                float c0 = fc[s0 * (HD / 2) + i2], sn0 = fs[s0 * (HD / 2) + i2];
                float c1 = fc[s1 * (HD / 2) + i2], sn1 = fs[s1 * (HD / 2) + i2];
                float t0 = a0 * c0 - a1 * sn0, t1 = a0 * sn0 + a1 * c0;
                float t2 = a2 * c1 - a3 * sn1, t3 = a2 * sn1 + a3 * c1;
                a0 = t0; a1 = t1; a2 = t2; a3 = t3;
            }
            if (MODE == 2) {
                float* C = (float*)Cv;
                *(float2*)(C + (size_t)r0 * N + col)       = make_float2(a0, a1);
                *(float2*)(C + (size_t)(r0 + 8) * N + col) = make_float2(a2, a3);
            } else {
                __half* C = (__half*)Cv;
                *(__half2*)(C + (size_t)r0 * N + col)       = __floats2half2_rn(a0, a1);
                *(__half2*)(C + (size_t)(r0 + 8) * N + col) = __floats2half2_rn(a2, a3);
            }
        }
    }
}

// ---------------- flash attention, fp16 mma, causal, GQA -------------------
// CTA: 128 Q rows, 8 warps x 16 rows; K/V tile 64. Grid (SEQ/128, NH, B).
// Compact q/k/v buffers. Longest-first (qt = 15 - bx). REG CAP = 2 CTAs/SM.
#define ATT_SMEM_BYTES 88064
__global__ __launch_bounds__(256, 2)
void attn_f16(const __half* __restrict__ q, const __half* __restrict__ k,
              const __half* __restrict__ v, __half* __restrict__ o) {
    extern __shared__ uint32_t smu[];
    uint32_t* sp = smu + 17408;
    const uint32_t sqb = smem_u32(smu);
    const uint32_t skb = sqb + 8704 * 4;
    const uint32_t svb = sqb + 13056 * 4;
    const uint32_t spb = sqb + 17408 * 4;

    const int tid  = threadIdx.x;
    const int lane = tid & 31, w = tid >> 5;
    const int g = lane >> 2, c = lane & 3;
    const int qt = (SEQ / 128 - 1) - blockIdx.x;   // longest first
    const int h = blockIdx.y, b = blockIdx.z;
    const int kv = h >> 2;
    const size_t rowbase = (size_t)b * SEQ;
    const int qrow0 = qt * 128;
    const int r0g = w * 16 + g;

    const int lmrow = (lane & 7) + ((lane >> 3) & 1) * 8;
    const int lmcol = (lane >> 4) * 4;
    const int krow  = (lane & 7) + (lane >> 4) * 8;
    const int kcolw = ((lane >> 3) & 1) * 4;
    const int vrow  = (lane & 7) + ((lane >> 3) & 1) * 8;
    const int vcolw = (lane >> 4) * 4;

    const int sr16 = tid >> 4, sch = tid & 15;

    #pragma unroll
    for (int p = 0; p < 8; p++) {
        int r = sr16 + 16 * p;
        CPA16(sqb + (uint32_t)(r * 272 + sch * 16),
              q + (rowbase + qrow0 + r) * (NH * HD) + h * HD + sch * 8);
    }
    CPA_COMMIT();

    float out[16][4] = {};
    float m0 = -1e30f, m1 = -1e30f, l0 = 0.f, l1 = 0.f;
    const float SCALE = 0.08838834764831845f;   // 1/sqrt(128)

    const int ktmax = 2 * qt + 1;
    for (int kt = 0; kt <= ktmax; kt++) {
        __syncthreads();
        #pragma unroll
        for (int p = 0; p < 4; p++) {
            int r = sr16 + 16 * p;
            size_t src = (rowbase + kt * 64 + r) * (NKV * HD) + kv * HD + sch * 8;
            CPA16(skb + (uint32_t)(r * 272 + sch * 16), k + src);
            CPA16(svb + (uint32_t)(r * 272 + sch * 16), v + src);
        }
        CPA_COMMIT();
        CPA_WAIT(0);
        __syncthreads();

        float s[8][4] = {};
        #pragma unroll
        for (int ks = 0; ks < 8; ks++) {
            uint32_t a[4];
            LDSM4(a[0], a[1], a[2], a[3],
                  sqb + (uint32_t)(((w * 16 + lmrow) * 68 + ks * 8 + lmcol) * 4));
            #pragma unroll
            for (int nfp = 0; nfp < 4; nfp++) {
                uint32_t b0, b1, b2, b3;
                LDSM4(b0, b1, b2, b3,
                      skb + (uint32_t)(((nfp * 16 + krow) * 68 + ks * 8 + kcolw) * 4));
                uint32_t bA[2] = {b0, b1}, bB[2] = {b2, b3};
                mma16(s[2 * nfp],     a, bA);
                mma16(s[2 * nfp + 1], a, bB);
            }
        }

        const bool needmask = (kt >= 2 * qt);
        const int grow0 = qrow0 + r0g, grow1 = grow0 + 8;
        #pragma unroll
        for (int nf = 0; nf < 8; nf++) {
            int col = kt * 64 + nf * 8 + 2 * c;
            s[nf][0] = (needmask && col     > grow0) ? -1e30f : s[nf][0] * SCALE;
            s[nf][1] = (needmask && col + 1 > grow0) ? -1e30f : s[nf][1] * SCALE;
            s[nf][2] = (needmask && col     > grow1) ? -1e30f : s[nf][2] * SCALE;
            s[nf][3] = (needmask && col + 1 > grow1) ? -1e30f : s[nf][3] * SCALE;
        }

        float rm0 = -1e30f, rm1 = -1e30f;
        #pragma unroll
        for (int nf = 0; nf < 8; nf++) {
            rm0 = fmaxf(rm0, fmaxf(s[nf][0], s[nf][1]));
            rm1 = fmaxf(rm1, fmaxf(s[nf][2], s[nf][3]));
        }
        #pragma unroll
        for (int off = 1; off < 4; off <<= 1) {
            rm0 = fmaxf(rm0, __shfl_xor_sync(0xffffffffu, rm0, off));
            rm1 = fmaxf(rm1, __shfl_xor_sync(0xffffffffu, rm1, off));
        }
        float mn0 = fmaxf(m0, rm0), mn1 = fmaxf(m1, rm1);
        float co0 = __expf(m0 - mn0), co1 = __expf(m1 - mn1);
        m0 = mn0; m1 = mn1;

        float rs0 = 0.f, rs1 = 0.f;
        #pragma unroll
        for (int nf = 0; nf < 8; nf++) {
            float p00 = __expf(s[nf][0] - mn0);
            float p01 = __expf(s[nf][1] - mn0);
            float p10 = __expf(s[nf][2] - mn1);
            float p11 = __expf(s[nf][3] - mn1);
            rs0 += p00 + p01;
            rs1 += p10 + p11;
            __half2 h0 = __floats2half2_rn(p00, p01);
            __half2 h1 = __floats2half2_rn(p10, p11);
            sp[r0g * 36 + nf * 4 + c]       = *(uint32_t*)&h0;
            sp[(r0g + 8) * 36 + nf * 4 + c] = *(uint32_t*)&h1;
        }
        #pragma unroll
        for (int off = 1; off < 4; off <<= 1) {
            rs0 += __shfl_xor_sync(0xffffffffu, rs0, off);
            rs1 += __shfl_xor_sync(0xffffffffu, rs1, off);
        }
        l0 = l0 * co0 + rs0;
        l1 = l1 * co1 + rs1;
        #pragma unroll
        for (int nf = 0; nf < 16; nf++) {
            out[nf][0] *= co0; out[nf][1] *= co0;
            out[nf][2] *= co1; out[nf][3] *= co1;
        }
        __syncwarp();

        #pragma unroll
        for (int ks = 0; ks < 4; ks++) {
            uint32_t a[4];
            LDSM4(a[0], a[1], a[2], a[3],
                  spb + (uint32_t)(((w * 16 + lmrow) * 36 + ks * 8 + lmcol) * 4));
            const uint32_t rowaddr = svb + (uint32_t)(((ks * 16 + vrow) * 68 + vcolw) * 4);
            #pragma unroll
            for (int nf2 = 0; nf2 < 8; nf2++) {
                uint32_t d0, d1, d2, d3;
                LDSM4T(d0, d1, d2, d3, rowaddr + (uint32_t)(nf2 * 32));
                uint32_t bA[2] = {d0, d1}, bB[2] = {d2, d3};
                mma16(out[2 * nf2],     a, bA);
                mma16(out[2 * nf2 + 1], a, bB);
            }
        }
        __syncwarp();
    }

    const float i0 = 1.f / l0, i1 = 1.f / l1;
    const size_t gr0 = rowbase + qrow0 + r0g;
    #pragma unroll
    for (int nf = 0; nf < 16; nf++) {
        const int col = h * HD + nf * 8 + 2 * c;
        *(__half2*)(o + gr0 * (NH * HD) + col) =
            __floats2half2_rn(out[nf][0] * i0, out[nf][1] * i0);
        *(__half2*)(o + (gr0 + 8) * (NH * HD) + col) =
            __floats2half2_rn(out[nf][2] * i1, out[nf][3] * i1);
    }
}

// ---------------- launch ----------------------------------------------------
extern "C" void kernel_launch(void* const* d_in, const int* in_sizes, int n_in,
                              void* d_out, int out_size) {
    const float* x  = (const float*)d_in[0];
    const float* fc = (const float*)d_in[1];
    const float* fs = (const float*)d_in[2];
    const float* wq = (const float*)d_in[3];
    const float* wk = (const float*)d_in[4];
    const float* wv = (const float*)d_in[5];
    const float* wo = (const float*)d_in[6];
    float* out = (float*)d_out;

    __half *xh, *wqh, *wkh, *wvh, *woh, *qh, *kh, *vh, *oh;
    cudaGetSymbolAddress((void**)&xh,  g_xh);
    cudaGetSymbolAddress((void**)&wqh, g_wqh);
    cudaGetSymbolAddress((void**)&wkh, g_wkh);
    cudaGetSymbolAddress((void**)&wvh, g_wvh);
    cudaGetSymbolAddress((void**)&woh, g_woh);
    cudaGetSymbolAddress((void**)&qh,  g_qh);
    cudaGetSymbolAddress((void**)&kh,  g_kh);
    cudaGetSymbolAddress((void**)&vh,  g_vh);
    cudaGetSymbolAddress((void**)&oh,  g_oh);

    cudaFuncSetAttribute(attn_f16, cudaFuncAttributeMaxDynamicSharedMemorySize,
                         ATT_SMEM_BYTES);
    cudaFuncSetAttribute(gemm_h<0>, cudaFuncAttributeMaxDynamicSharedMemorySize,
                         GEMM_SMEM_BYTES);
    cudaFuncSetAttribute(gemm_h<1>, cudaFuncAttributeMaxDynamicSharedMemorySize,
                         GEMM_SMEM_BYTES);
    cudaFuncSetAttribute(gemm_h<2>, cudaFuncAttributeMaxDynamicSharedMemorySize,
                         GEMM_SMEM_BYTES);

    // convert all inputs to half in one launch
    f2h5<<<(C5 + 255) / 256, 256>>>(x, xh, wq, wqh, wk, wkh, wv, wvh, wo, woh);

    // projections; RoPE fused into Q and K epilogues
    gemm_h<1><<<dim3((NH  * HD) / 128, MROWS / 128), 256, GEMM_SMEM_BYTES>>>(
        xh, wqh, qh, NH * HD, DMODEL, fc, fs);
    gemm_h<1><<<dim3((NKV * HD) / 128, MROWS / 128), 256, GEMM_SMEM_BYTES>>>(
        xh, wkh, kh, NKV * HD, DMODEL, fc, fs);
    gemm_h<0><<<dim3((NKV * HD) / 128, MROWS / 128), 256, GEMM_SMEM_BYTES>>>(
        xh, wvh, vh, NKV * HD, DMODEL, nullptr, nullptr);

    // attention (compact buffers, longest-first, 2 CTAs/SM guaranteed)
    attn_f16<<<dim3(SEQ / 128, NH, BATCH), 256, ATT_SMEM_BYTES>>>(qh, kh, vh, oh);

    // output projection (float out)
    gemm_h<2><<<dim3(DMODEL / 128, MROWS / 128), 256, GEMM_SMEM_BYTES>>>(
        oh, woh, out, DMODEL, DMODEL, nullptr, nullptr);
}